// round 1
// baseline (speedup 1.0000x reference)
#include <cuda_runtime.h>
#include <cstddef>

#define B_   1024
#define T_   2048
#define CIN  9
#define C1   16
#define C2   32
#define RT   512
#define HID  128
#define OUTF 64

#define DINV2 0.7071067811865475f   // 1/sqrt(2)
#define DINV3 0.5773502691896258f   // 1/sqrt(3)

// ---------------- scratch (static device allocations; no cudaMalloc) ----------------
__device__ float g_h1[(size_t)B_ * C1 * 1024];      // conv1 output, pooled  [B][16][1024]  ~67MB
__device__ float g_h2[(size_t)B_ * RT * C2];        // conv2 output, node-major [B*512][32] ~67MB
__device__ float g_part[(size_t)B_ * 16 * HID];     // per-(chunk,half) partial sums  ~8MB

// ---------------- conv1: 9->16 k5 pad2 + relu + maxpool2 ----------------
__global__ void __launch_bounds__(256) conv1_kernel(const float* __restrict__ x,
                                                    const float* __restrict__ w,
                                                    const float* __restrict__ bias) {
    const int b = blockIdx.y, cx = blockIdx.x;      // chunk of 512 taus
    __shared__ float xs[CIN][516];
    __shared__ float ws[C1 * 45];
    __shared__ float bs[C1];
    const int tid = threadIdx.x;

    for (int i = tid; i < C1 * 45; i += 256) ws[i] = w[i];
    if (tid < C1) bs[tid] = bias[tid];
    const float* xb = x + (size_t)b * CIN * T_;
    for (int i = tid; i < CIN * 516; i += 256) {
        int ci = i / 516, j = i % 516;
        int tg = cx * 512 + j - 2;
        xs[ci][j] = ((unsigned)tg < T_) ? xb[ci * T_ + tg] : 0.f;
    }
    __syncthreads();

    for (int oi = tid; oi < C1 * 256; oi += 256) {
        const int co = oi >> 8, p = oi & 255;
        const int tau = 2 * p;
        float y0 = bs[co], y1 = bs[co];
        const float* wc = &ws[co * 45];
#pragma unroll
        for (int ci = 0; ci < CIN; ci++) {
            const float* xr = &xs[ci][tau];
            float x0 = xr[0], x1 = xr[1], x2 = xr[2], x3 = xr[3], x4 = xr[4], x5 = xr[5];
            float w0 = wc[ci*5+0], w1 = wc[ci*5+1], w2 = wc[ci*5+2], w3 = wc[ci*5+3], w4 = wc[ci*5+4];
            y0 = fmaf(x0,w0,y0); y0 = fmaf(x1,w1,y0); y0 = fmaf(x2,w2,y0); y0 = fmaf(x3,w3,y0); y0 = fmaf(x4,w4,y0);
            y1 = fmaf(x1,w0,y1); y1 = fmaf(x2,w1,y1); y1 = fmaf(x3,w2,y1); y1 = fmaf(x4,w3,y1); y1 = fmaf(x5,w4,y1);
        }
        float v = fmaxf(fmaxf(y0, y1), 0.f);
        g_h1[((size_t)b * C1 + co) * 1024 + cx * 256 + p] = v;
    }
}

// ---------------- conv2: 16->32 k5 pad2 + relu + maxpool2, node-major output ----------------
__global__ void __launch_bounds__(256) conv2_kernel(const float* __restrict__ w,
                                                    const float* __restrict__ bias) {
    const int b = blockIdx.y, cx = blockIdx.x;      // chunk of 512 taus (tau in [0,1024))
    __shared__ float xs[C1][516];                   // 33024 B
    __shared__ float wt[C1 * 5 * C2];               // transposed [ci][k][co], 10240 B
    __shared__ float bs[C2];
    const int tid = threadIdx.x;

    for (int i = tid; i < C2 * C1 * 5; i += 256) {
        int co = i / 80, r = i % 80;                // r = ci*5+k
        wt[r * C2 + co] = w[i];
    }
    if (tid < C2) bs[tid] = bias[tid];
    const float* hb = g_h1 + (size_t)b * C1 * 1024;
    for (int i = tid; i < C1 * 516; i += 256) {
        int ci = i / 516, j = i % 516;
        int tg = cx * 512 + j - 2;
        xs[ci][j] = ((unsigned)tg < 1024) ? hb[ci * 1024 + tg] : 0.f;
    }
    __syncthreads();

    const int co = tid & 31;
    const float bv = bs[co];
    for (int it = 0; it < 32; it++) {
        const int p = (tid >> 5) + it * 8;
        const int tau = 2 * p;
        float y0 = bv, y1 = bv;
#pragma unroll
        for (int ci = 0; ci < C1; ci++) {
            const float* xr = &xs[ci][tau];
            const float* wc = &wt[ci * 5 * C2];
            float x0 = xr[0], x1 = xr[1], x2 = xr[2], x3 = xr[3], x4 = xr[4], x5 = xr[5];
            float w0 = wc[0*C2+co], w1 = wc[1*C2+co], w2 = wc[2*C2+co], w3 = wc[3*C2+co], w4 = wc[4*C2+co];
            y0 = fmaf(x0,w0,y0); y0 = fmaf(x1,w1,y0); y0 = fmaf(x2,w2,y0); y0 = fmaf(x3,w3,y0); y0 = fmaf(x4,w4,y0);
            y1 = fmaf(x1,w0,y1); y1 = fmaf(x2,w1,y1); y1 = fmaf(x3,w2,y1); y1 = fmaf(x4,w3,y1); y1 = fmaf(x5,w4,y1);
        }
        float v = fmaxf(fmaxf(y0, y1), 0.f);
        g_h2[((size_t)b * RT + cx * 256 + p) * C2 + co] = v;   // coalesced: lanes = consecutive co
    }
}

// ---------------- fused GCN1 + GCN2 + time-mean partial ----------------
// Per CTA: one sample b, one 64-t chunk. Computes z1 with 2-row halo (68 rows),
// stencil+relu -> g1 (66 rows), z2 (66 rows), stencil+relu -> g2 (64 rows), row-sum.
__device__ __forceinline__ void stencil_coeffs(int t, float& cL, float& cS, float& cR) {
    float dt = (t == 0 || t == RT - 1) ? DINV2 : DINV3;
    cS = dt * dt;
    cL = (t > 0)      ? dt * ((t - 1 == 0)      ? DINV2 : DINV3) : 0.f;
    cR = (t < RT - 1) ? dt * ((t + 1 == RT - 1) ? DINV2 : DINV3) : 0.f;
}

__global__ void __launch_bounds__(256, 1) gcn_fused_kernel(
    const float* __restrict__ W1, const float* __restrict__ b1,
    const float* __restrict__ W2, const float* __restrict__ b2) {
    extern __shared__ float sm[];
    float* in_s = sm;                    // 68*32   = 2176
    float* W1_s = in_s + 68 * 32;        // 32*128  = 4096
    float* W2_s = W1_s + 4096;           // 128*128 = 16384
    float* z_s  = W2_s + 16384;          // 68*128  = 8704  (reused for z2)
    float* g1_s = z_s + 68 * 128;        // 66*128  = 8448
    float* b1_s = g1_s + 66 * 128;       // 128
    float* b2_s = b1_s + 128;            // 128     -> total 40064 floats = 160256 B

    const int tid = threadIdx.x;
    const int b = blockIdx.y, chunk = blockIdx.x;
    const int t0 = chunk * 64;

    for (int i = tid; i < 32 * HID; i += 256) W1_s[i] = W1[i];
    for (int i = tid; i < HID * HID; i += 256) W2_s[i] = W2[i];
    if (tid < HID) { b1_s[tid] = b1[tid]; b2_s[tid] = b2[tid]; }
    for (int i = tid; i < 68 * 32; i += 256) {
        int r = i >> 5, c = i & 31;
        int t = t0 - 2 + r;
        in_s[i] = ((unsigned)t < RT) ? g_h2[((size_t)b * RT + t) * C2 + c] : 0.f;
    }
    __syncthreads();

    const int lane = tid & 31, warp = tid >> 5;

    // GEMM1: z1[68][128] = in[68][32] @ W1[32][128]
    {
        const float4* W1v = (const float4*)W1_s;
        float4* zv = (float4*)z_s;
#pragma unroll
        for (int j = 0; j < 9; j++) {
            int i = warp + j * 8;
            if (i < 68) {
                float4 acc = make_float4(0.f, 0.f, 0.f, 0.f);
                const float* inrow = in_s + i * 32;
#pragma unroll
                for (int k = 0; k < 32; k++) {
                    float a = inrow[k];
                    float4 wv = W1v[k * 32 + lane];
                    acc.x = fmaf(a, wv.x, acc.x); acc.y = fmaf(a, wv.y, acc.y);
                    acc.z = fmaf(a, wv.z, acc.z); acc.w = fmaf(a, wv.w, acc.w);
                }
                zv[i * 32 + lane] = acc;
            }
        }
    }
    __syncthreads();

    // g1[j][f], j in [0,66), t = t0-1+j. z row i <-> t0-2+i.
    for (int e = tid; e < 66 * HID; e += 256) {
        int j = e >> 7, f = e & 127;
        int t = t0 - 1 + j;
        float g = 0.f;
        if ((unsigned)t < RT) {
            float cL, cS, cR; stencil_coeffs(t, cL, cS, cR);
            g = fmaf(cL, z_s[j * HID + f],
                fmaf(cS, z_s[(j + 1) * HID + f],
                fmaf(cR, z_s[(j + 2) * HID + f], b1_s[f])));
            g = fmaxf(g, 0.f);
        }
        g1_s[e] = g;
    }
    __syncthreads();

    // GEMM2: z2[66][128] = g1[66][128] @ W2[128][128]  (writes into z_s)
    {
        const float4* W2v = (const float4*)W2_s;
        float4* zv = (float4*)z_s;
#pragma unroll
        for (int j = 0; j < 9; j++) {
            int i = warp + j * 8;
            if (i < 66) {
                float4 acc = make_float4(0.f, 0.f, 0.f, 0.f);
                const float* grow = g1_s + i * HID;
#pragma unroll 8
                for (int k = 0; k < HID; k++) {
                    float a = grow[k];
                    float4 wv = W2v[k * 32 + lane];
                    acc.x = fmaf(a, wv.x, acc.x); acc.y = fmaf(a, wv.y, acc.y);
                    acc.z = fmaf(a, wv.z, acc.z); acc.w = fmaf(a, wv.w, acc.w);
                }
                zv[i * 32 + lane] = acc;
            }
        }
    }
    __syncthreads();

    // final stencil + relu + partial sum over 64 t-rows (deterministic, no atomics)
    {
        const int f = tid & 127, half = tid >> 7;
        const float bv = b2_s[f];
        float s = 0.f;
#pragma unroll 4
        for (int r = 0; r < 32; r++) {
            int t = t0 + half * 32 + r;
            int i2 = half * 32 + r + 1;          // z2 row for t (z2 row i <-> t0-1+i)
            float cL, cS, cR; stencil_coeffs(t, cL, cS, cR);
            float g = fmaf(cL, z_s[(i2 - 1) * HID + f],
                      fmaf(cS, z_s[i2 * HID + f],
                      fmaf(cR, z_s[(i2 + 1) * HID + f], bv)));
            s += fmaxf(g, 0.f);
        }
        g_part[((size_t)(b * 16) + chunk * 2 + half) * HID + f] = s;
    }
}

// ---------------- mean + FC ----------------
__global__ void __launch_bounds__(128) fc_kernel(const float* __restrict__ fcw,
                                                 const float* __restrict__ fcb,
                                                 float* __restrict__ out) {
    const int b = blockIdx.x, tid = threadIdx.x;
    __shared__ float mean_s[HID];
    float s = 0.f;
#pragma unroll
    for (int i = 0; i < 16; i++) s += g_part[((size_t)b * 16 + i) * HID + tid];
    mean_s[tid] = s * (1.f / (float)RT);
    __syncthreads();
    if (tid < OUTF) {
        float acc = fcb[tid];
#pragma unroll 8
        for (int f = 0; f < HID; f++) acc = fmaf(mean_s[f], fcw[f * OUTF + tid], acc);
        out[(size_t)b * OUTF + tid] = acc;
    }
}

// ---------------- launch ----------------
extern "C" void kernel_launch(void* const* d_in, const int* in_sizes, int n_in,
                              void* d_out, int out_size) {
    const float* x       = (const float*)d_in[0];
    const float* conv1_w = (const float*)d_in[1];
    const float* conv1_b = (const float*)d_in[2];
    const float* conv2_w = (const float*)d_in[3];
    const float* conv2_b = (const float*)d_in[4];
    const float* gcn1_w  = (const float*)d_in[5];
    const float* gcn1_b  = (const float*)d_in[6];
    const float* gcn2_w  = (const float*)d_in[7];
    const float* gcn2_b  = (const float*)d_in[8];
    const float* fc_w    = (const float*)d_in[9];
    const float* fc_b    = (const float*)d_in[10];
    float* out = (float*)d_out;

    static bool attr_set = false;
    if (!attr_set) {
        cudaFuncSetAttribute(gcn_fused_kernel,
                             cudaFuncAttributeMaxDynamicSharedMemorySize, 160256);
        attr_set = true;
    }

    conv1_kernel<<<dim3(4, B_), 256>>>(x, conv1_w, conv1_b);
    conv2_kernel<<<dim3(2, B_), 256>>>(conv2_w, conv2_b);
    gcn_fused_kernel<<<dim3(8, B_), 256, 160256>>>(gcn1_w, gcn1_b, gcn2_w, gcn2_b);
    fc_kernel<<<B_, 128>>>(fc_w, fc_b, out);
}

// round 2
// speedup vs baseline: 1.9667x; 1.9667x over previous
#include <cuda_runtime.h>
#include <cstddef>

#define B_   1024
#define T_   2048
#define CIN  9
#define C1   16
#define C2   32
#define RT   512
#define HID  128
#define OUTF 64

#define DINV2 0.7071067811865475f   // 1/sqrt(2)
#define DINV3 0.5773502691896258f   // 1/sqrt(3)

// ---------------- scratch ----------------
__device__ float g_h1[(size_t)B_ * C1 * 1024];
__device__ float g_h2[(size_t)B_ * RT * C2];
__device__ float g_part[(size_t)B_ * 8 * HID];

// ---------------- helpers ----------------
__device__ __forceinline__ unsigned f2tf32(float x) {
    unsigned u; asm("cvt.rna.tf32.f32 %0, %1;" : "=r"(u) : "f"(x)); return u;
}
__device__ __forceinline__ void mma_tf32(float c[4], unsigned a0, unsigned a1,
                                         unsigned a2, unsigned a3,
                                         unsigned b0, unsigned b1) {
    asm volatile("mma.sync.aligned.m16n8k8.row.col.f32.tf32.tf32.f32 "
                 "{%0,%1,%2,%3},{%4,%5,%6,%7},{%8,%9},{%0,%1,%2,%3};"
                 : "+f"(c[0]), "+f"(c[1]), "+f"(c[2]), "+f"(c[3])
                 : "r"(a0), "r"(a1), "r"(a2), "r"(a3), "r"(b0), "r"(b1));
}

// ---------------- conv1: 9->16 k5 pad2 + relu + maxpool2 (unchanged) ----------------
__global__ void __launch_bounds__(256) conv1_kernel(const float* __restrict__ x,
                                                    const float* __restrict__ w,
                                                    const float* __restrict__ bias) {
    const int b = blockIdx.y, cx = blockIdx.x;
    __shared__ float xs[CIN][516];
    __shared__ float ws[C1 * 45];
    __shared__ float bs[C1];
    const int tid = threadIdx.x;

    for (int i = tid; i < C1 * 45; i += 256) ws[i] = w[i];
    if (tid < C1) bs[tid] = bias[tid];
    const float* xb = x + (size_t)b * CIN * T_;
    for (int i = tid; i < CIN * 516; i += 256) {
        int ci = i / 516, j = i % 516;
        int tg = cx * 512 + j - 2;
        xs[ci][j] = ((unsigned)tg < T_) ? xb[ci * T_ + tg] : 0.f;
    }
    __syncthreads();

    for (int oi = tid; oi < C1 * 256; oi += 256) {
        const int co = oi >> 8, p = oi & 255;
        const int tau = 2 * p;
        float y0 = bs[co], y1 = bs[co];
        const float* wc = &ws[co * 45];
#pragma unroll
        for (int ci = 0; ci < CIN; ci++) {
            const float* xr = &xs[ci][tau];
            float x0 = xr[0], x1 = xr[1], x2 = xr[2], x3 = xr[3], x4 = xr[4], x5 = xr[5];
            float w0 = wc[ci*5+0], w1 = wc[ci*5+1], w2 = wc[ci*5+2], w3 = wc[ci*5+3], w4 = wc[ci*5+4];
            y0 = fmaf(x0,w0,y0); y0 = fmaf(x1,w1,y0); y0 = fmaf(x2,w2,y0); y0 = fmaf(x3,w3,y0); y0 = fmaf(x4,w4,y0);
            y1 = fmaf(x1,w0,y1); y1 = fmaf(x2,w1,y1); y1 = fmaf(x3,w2,y1); y1 = fmaf(x4,w3,y1); y1 = fmaf(x5,w4,y1);
        }
        float v = fmaxf(fmaxf(y0, y1), 0.f);
        g_h1[((size_t)b * C1 + co) * 1024 + cx * 256 + p] = v;
    }
}

// ---------------- conv2: 16->32 k5 pad2 + relu + maxpool2 (unchanged) ----------------
__global__ void __launch_bounds__(256) conv2_kernel(const float* __restrict__ w,
                                                    const float* __restrict__ bias) {
    const int b = blockIdx.y, cx = blockIdx.x;
    __shared__ float xs[C1][516];
    __shared__ float wt[C1 * 5 * C2];
    __shared__ float bs[C2];
    const int tid = threadIdx.x;

    for (int i = tid; i < C2 * C1 * 5; i += 256) {
        int co = i / 80, r = i % 80;
        wt[r * C2 + co] = w[i];
    }
    if (tid < C2) bs[tid] = bias[tid];
    const float* hb = g_h1 + (size_t)b * C1 * 1024;
    for (int i = tid; i < C1 * 516; i += 256) {
        int ci = i / 516, j = i % 516;
        int tg = cx * 512 + j - 2;
        xs[ci][j] = ((unsigned)tg < 1024) ? hb[ci * 1024 + tg] : 0.f;
    }
    __syncthreads();

    const int co = tid & 31;
    const float bv = bs[co];
    for (int it = 0; it < 32; it++) {
        const int p = (tid >> 5) + it * 8;
        const int tau = 2 * p;
        float y0 = bv, y1 = bv;
#pragma unroll
        for (int ci = 0; ci < C1; ci++) {
            const float* xr = &xs[ci][tau];
            const float* wc = &wt[ci * 5 * C2];
            float x0 = xr[0], x1 = xr[1], x2 = xr[2], x3 = xr[3], x4 = xr[4], x5 = xr[5];
            float w0 = wc[0*C2+co], w1 = wc[1*C2+co], w2 = wc[2*C2+co], w3 = wc[3*C2+co], w4 = wc[4*C2+co];
            y0 = fmaf(x0,w0,y0); y0 = fmaf(x1,w1,y0); y0 = fmaf(x2,w2,y0); y0 = fmaf(x3,w3,y0); y0 = fmaf(x4,w4,y0);
            y1 = fmaf(x1,w0,y1); y1 = fmaf(x2,w1,y1); y1 = fmaf(x3,w2,y1); y1 = fmaf(x4,w3,y1); y1 = fmaf(x5,w4,y1);
        }
        float v = fmaxf(fmaxf(y0, y1), 0.f);
        g_h2[((size_t)b * RT + cx * 256 + p) * C2 + co] = v;
    }
}

// ---------------- fused GCN1 + GCN2 + time-mean partial (tf32 MMA) ----------------
__device__ __forceinline__ void stencil_coeffs(int t, float& cL, float& cS, float& cR) {
    float dt = (t == 0 || t == RT - 1) ? DINV2 : DINV3;
    cS = dt * dt;
    cL = (t > 0)      ? dt * ((t - 1 == 0)      ? DINV2 : DINV3) : 0.f;
    cR = (t < RT - 1) ? dt * ((t + 1 == RT - 1) ? DINV2 : DINV3) : 0.f;
}

// smem layout (floats):
//  W2s : [128][136]  0      .. 17408
//  W1s : [32][136]   17408  .. 21760
//  zs  : [132][132]  21760  .. 39184
//  g1s : [132][132]  39184  .. 56608   (in_s [132][36] aliases g1s)
//  b1s : 128, b2s : 128                -> total 56864 floats = 227456 B
#define SW  136
#define SZ  132
#define SIN 36
#define GCN_SMEM_BYTES (56864 * 4)

__global__ void __launch_bounds__(256, 1) gcn_fused_kernel(
    const float* __restrict__ W1, const float* __restrict__ b1,
    const float* __restrict__ W2, const float* __restrict__ b2) {
    extern __shared__ float sm[];
    float* W2s = sm;
    float* W1s = sm + 17408;
    float* zs  = sm + 21760;
    float* g1s = sm + 39184;
    float* in_s = g1s;                 // alias: in_s dead before g1s written
    float* b1s = sm + 56608;
    float* b2s = sm + 56736;

    const int tid = threadIdx.x;
    const int b = blockIdx.y, chunk = blockIdx.x;
    const int t0 = chunk * 128;

    // ---- loads (tf32-rounded) ----
    for (int i = tid; i < HID * HID; i += 256) {
        int r = i >> 7, c = i & 127;
        W2s[r * SW + c] = __uint_as_float(f2tf32(W2[i]));
    }
    for (int i = tid; i < 32 * HID; i += 256) {
        int r = i >> 7, c = i & 127;
        W1s[r * SW + c] = __uint_as_float(f2tf32(W1[i]));
    }
    if (tid < HID) { b1s[tid] = b1[tid]; b2s[tid] = b2[tid]; }
    for (int i = tid; i < 132 * 32; i += 256) {
        int r = i >> 5, c = i & 31;
        int t = t0 - 2 + r;
        float v = ((unsigned)t < RT) ? g_h2[((size_t)b * RT + t) * C2 + c] : 0.f;
        in_s[r * SIN + c] = __uint_as_float(f2tf32(v));
    }
    __syncthreads();

    const int w = tid >> 5, lane = tid & 31;
    const int gq = lane >> 2, tq = lane & 3;
    const int n0 = (w & 1) * 64, mg = w >> 1;   // m-tiles mg, mg+4

    // ================= GEMM1: z1[0..127] = in[.,32] @ W1[32,128] =================
    {
        float acc[2][8][4];
#pragma unroll
        for (int mt = 0; mt < 2; mt++)
#pragma unroll
            for (int nt = 0; nt < 8; nt++)
#pragma unroll
                for (int q = 0; q < 4; q++) acc[mt][nt][q] = 0.f;

#pragma unroll
        for (int ks = 0; ks < 4; ks++) {
            unsigned bf[8][2];
#pragma unroll
            for (int nt = 0; nt < 8; nt++) {
                int nc = n0 + nt * 8 + gq;
                bf[nt][0] = __float_as_uint(W1s[(ks * 8 + tq) * SW + nc]);
                bf[nt][1] = __float_as_uint(W1s[(ks * 8 + tq + 4) * SW + nc]);
            }
#pragma unroll
            for (int mt = 0; mt < 2; mt++) {
                int r0 = (mg + mt * 4) * 16;
                unsigned a0 = __float_as_uint(in_s[(r0 + gq) * SIN + ks * 8 + tq]);
                unsigned a1 = __float_as_uint(in_s[(r0 + gq + 8) * SIN + ks * 8 + tq]);
                unsigned a2 = __float_as_uint(in_s[(r0 + gq) * SIN + ks * 8 + tq + 4]);
                unsigned a3 = __float_as_uint(in_s[(r0 + gq + 8) * SIN + ks * 8 + tq + 4]);
#pragma unroll
                for (int nt = 0; nt < 8; nt++)
                    mma_tf32(acc[mt][nt], a0, a1, a2, a3, bf[nt][0], bf[nt][1]);
            }
        }
#pragma unroll
        for (int mt = 0; mt < 2; mt++) {
            int r0 = (mg + mt * 4) * 16;
#pragma unroll
            for (int nt = 0; nt < 8; nt++) {
                int c0 = n0 + nt * 8 + tq * 2;
                zs[(r0 + gq) * SZ + c0]     = acc[mt][nt][0];
                zs[(r0 + gq) * SZ + c0 + 1] = acc[mt][nt][1];
                zs[(r0 + gq + 8) * SZ + c0]     = acc[mt][nt][2];
                zs[(r0 + gq + 8) * SZ + c0 + 1] = acc[mt][nt][3];
            }
        }
    }
    // tail rows 128..131 of z1 (scalar)
    for (int e = tid; e < 4 * HID; e += 256) {
        int i = 128 + (e >> 7), c = e & 127;
        int t = t0 - 2 + i;
        float s = 0.f;
        if ((unsigned)t < RT) {
#pragma unroll 8
            for (int k = 0; k < 32; k++) s = fmaf(in_s[i * SIN + k], W1s[k * SW + c], s);
        }
        zs[i * SZ + c] = s;
    }
    __syncthreads();

    // ---- stencil1 + bias + relu -> g1 rows 0..129 (tf32-rounded) ----
    for (int e = tid; e < 130 * HID; e += 256) {
        int j = e >> 7, f = e & 127;
        int t = t0 - 1 + j;
        float g = 0.f;
        if ((unsigned)t < RT) {
            float cL, cS, cR; stencil_coeffs(t, cL, cS, cR);
            g = fmaf(cL, zs[j * SZ + f],
                fmaf(cS, zs[(j + 1) * SZ + f],
                fmaf(cR, zs[(j + 2) * SZ + f], b1s[f])));
            g = fmaxf(g, 0.f);
        }
        g1s[j * SZ + f] = __uint_as_float(f2tf32(g));
    }
    __syncthreads();

    // ================= GEMM2: z2[0..127] = g1[.,128] @ W2[128,128] =================
    {
        float acc[2][8][4];
#pragma unroll
        for (int mt = 0; mt < 2; mt++)
#pragma unroll
            for (int nt = 0; nt < 8; nt++)
#pragma unroll
                for (int q = 0; q < 4; q++) acc[mt][nt][q] = 0.f;

#pragma unroll
        for (int ks = 0; ks < 16; ks++) {
            unsigned bf[8][2];
#pragma unroll
            for (int nt = 0; nt < 8; nt++) {
                int nc = n0 + nt * 8 + gq;
                bf[nt][0] = __float_as_uint(W2s[(ks * 8 + tq) * SW + nc]);
                bf[nt][1] = __float_as_uint(W2s[(ks * 8 + tq + 4) * SW + nc]);
            }
#pragma unroll
            for (int mt = 0; mt < 2; mt++) {
                int r0 = (mg + mt * 4) * 16;
                unsigned a0 = __float_as_uint(g1s[(r0 + gq) * SZ + ks * 8 + tq]);
                unsigned a1 = __float_as_uint(g1s[(r0 + gq + 8) * SZ + ks * 8 + tq]);
                unsigned a2 = __float_as_uint(g1s[(r0 + gq) * SZ + ks * 8 + tq + 4]);
                unsigned a3 = __float_as_uint(g1s[(r0 + gq + 8) * SZ + ks * 8 + tq + 4]);
#pragma unroll
                for (int nt = 0; nt < 8; nt++)
                    mma_tf32(acc[mt][nt], a0, a1, a2, a3, bf[nt][0], bf[nt][1]);
            }
        }
#pragma unroll
        for (int mt = 0; mt < 2; mt++) {
            int r0 = (mg + mt * 4) * 16;
#pragma unroll
            for (int nt = 0; nt < 8; nt++) {
                int c0 = n0 + nt * 8 + tq * 2;
                zs[(r0 + gq) * SZ + c0]     = acc[mt][nt][0];
                zs[(r0 + gq) * SZ + c0 + 1] = acc[mt][nt][1];
                zs[(r0 + gq + 8) * SZ + c0]     = acc[mt][nt][2];
                zs[(r0 + gq + 8) * SZ + c0 + 1] = acc[mt][nt][3];
            }
        }
    }
    // tail rows 128,129 of z2 (scalar)
    {
        int i2 = 128 + (tid >> 7), c = tid & 127;
        int t = t0 - 1 + i2;
        float s = 0.f;
        if ((unsigned)t < RT) {
#pragma unroll 8
            for (int k = 0; k < HID; k++) s = fmaf(g1s[i2 * SZ + k], W2s[k * SW + c], s);
        }
        zs[i2 * SZ + c] = s;
    }
    __syncthreads();

    // ---- final stencil + relu + partial sum over 64 rows each (deterministic) ----
    {
        const int f = tid & 127, half = tid >> 7;
        const float bv = b2s[f];
        float s = 0.f;
#pragma unroll 4
        for (int r = 0; r < 64; r++) {
            int t = t0 + half * 64 + r;
            int i2 = half * 64 + r + 1;          // z2 row i2 <-> t0-1+i2
            float cL, cS, cR; stencil_coeffs(t, cL, cS, cR);
            float g = fmaf(cL, zs[(i2 - 1) * SZ + f],
                      fmaf(cS, zs[i2 * SZ + f],
                      fmaf(cR, zs[(i2 + 1) * SZ + f], bv)));
            s += fmaxf(g, 0.f);
        }
        g_part[((size_t)(b * 8) + chunk * 2 + half) * HID + f] = s;
    }
}

// ---------------- mean + FC ----------------
__global__ void __launch_bounds__(128) fc_kernel(const float* __restrict__ fcw,
                                                 const float* __restrict__ fcb,
                                                 float* __restrict__ out) {
    const int b = blockIdx.x, tid = threadIdx.x;
    __shared__ float mean_s[HID];
    float s = 0.f;
#pragma unroll
    for (int i = 0; i < 8; i++) s += g_part[((size_t)b * 8 + i) * HID + tid];
    mean_s[tid] = s * (1.f / (float)RT);
    __syncthreads();
    if (tid < OUTF) {
        float acc = fcb[tid];
#pragma unroll 8
        for (int f = 0; f < HID; f++) acc = fmaf(mean_s[f], fcw[f * OUTF + tid], acc);
        out[(size_t)b * OUTF + tid] = acc;
    }
}

// ---------------- launch ----------------
extern "C" void kernel_launch(void* const* d_in, const int* in_sizes, int n_in,
                              void* d_out, int out_size) {
    const float* x       = (const float*)d_in[0];
    const float* conv1_w = (const float*)d_in[1];
    const float* conv1_b = (const float*)d_in[2];
    const float* conv2_w = (const float*)d_in[3];
    const float* conv2_b = (const float*)d_in[4];
    const float* gcn1_w  = (const float*)d_in[5];
    const float* gcn1_b  = (const float*)d_in[6];
    const float* gcn2_w  = (const float*)d_in[7];
    const float* gcn2_b  = (const float*)d_in[8];
    const float* fc_w    = (const float*)d_in[9];
    const float* fc_b    = (const float*)d_in[10];
    float* out = (float*)d_out;

    static bool attr_set = false;
    if (!attr_set) {
        cudaFuncSetAttribute(gcn_fused_kernel,
                             cudaFuncAttributeMaxDynamicSharedMemorySize, GCN_SMEM_BYTES);
        attr_set = true;
    }

    conv1_kernel<<<dim3(4, B_), 256>>>(x, conv1_w, conv1_b);
    conv2_kernel<<<dim3(2, B_), 256>>>(conv2_w, conv2_b);
    gcn_fused_kernel<<<dim3(4, B_), 256, GCN_SMEM_BYTES>>>(gcn1_w, gcn1_b, gcn2_w, gcn2_b);
    fc_kernel<<<B_, 128>>>(fc_w, fc_b, out);
}

// round 4
// speedup vs baseline: 2.4422x; 1.2418x over previous
#include <cuda_runtime.h>
#include <cstddef>

#define B_   1024
#define T_   2048
#define CIN  9
#define C1   16
#define C2   32
#define RT   512
#define HID  128
#define OUTF 64

#define DINV2 0.7071067811865475f
#define DINV3 0.5773502691896258f

// ---------------- scratch ----------------
__device__ float g_h1[(size_t)B_ * C1 * 1024];   // conv1 pooled out (tf32-rounded)
__device__ float g_h2[(size_t)B_ * RT * C2];     // conv2 pooled out, node-major
__device__ float g_part[(size_t)B_ * 8 * HID];

// ---------------- helpers ----------------
__device__ __forceinline__ unsigned f2tf32(float x) {
    unsigned u; asm("cvt.rna.tf32.f32 %0, %1;" : "=r"(u) : "f"(x)); return u;
}
__device__ __forceinline__ void mma_tf32(float c[4], unsigned a0, unsigned a1,
                                         unsigned a2, unsigned a3,
                                         unsigned b0, unsigned b1) {
    asm volatile("mma.sync.aligned.m16n8k8.row.col.f32.tf32.tf32.f32 "
                 "{%0,%1,%2,%3},{%4,%5,%6,%7},{%8,%9},{%0,%1,%2,%3};"
                 : "+f"(c[0]), "+f"(c[1]), "+f"(c[2]), "+f"(c[3])
                 : "r"(a0), "r"(a1), "r"(a2), "r"(a3), "r"(b0), "r"(b1));
}

// ================= conv1 (MMA): 9->16 k5 pad2 + relu + maxpool2 =================
// A = W[16 co][K=48], B = x[K][8 positions], C = [co][pos]; pool in-register.
// K = ci*5+tap; xs row 9 is a zero pad row for k>=45.
#define XS1_STRIDE 524
__global__ void __launch_bounds__(256) conv1_kernel(const float* __restrict__ x,
                                                    const float* __restrict__ w,
                                                    const float* __restrict__ bias) {
    const int b = blockIdx.y, cx = blockIdx.x;       // chunk of 512 conv positions
    __shared__ float xs[10 * XS1_STRIDE];
    const int tid = threadIdx.x;

    const float* xb = x + (size_t)b * CIN * T_;
    for (int i = tid; i < 10 * 516; i += 256) {
        int r = i / 516, j = i % 516;
        int tg = cx * 512 + j - 2;
        float v = (r < 9 && (unsigned)tg < T_) ? xb[r * T_ + tg] : 0.f;
        xs[r * XS1_STRIDE + j] = __uint_as_float(f2tf32(v));
    }

    const int lane = tid & 31, warp = tid >> 5;
    const int gq = lane >> 2, tq = lane & 3;

    unsigned aw[6][4];
    int boff0[6], boff1[6];
#pragma unroll
    for (int ks = 0; ks < 6; ks++) {
        int k0 = ks * 8 + tq, k1 = k0 + 4;
        aw[ks][0] = (k0 < 45) ? f2tf32(w[gq * 45 + k0])       : 0u;
        aw[ks][1] = (k0 < 45) ? f2tf32(w[(gq + 8) * 45 + k0]) : 0u;
        aw[ks][2] = (k1 < 45) ? f2tf32(w[gq * 45 + k1])       : 0u;
        aw[ks][3] = (k1 < 45) ? f2tf32(w[(gq + 8) * 45 + k1]) : 0u;
        boff0[ks] = (k0 / 5) * XS1_STRIDE + (k0 % 5);
        boff1[ks] = (k1 / 5) * XS1_STRIDE + (k1 % 5);
    }
    const float bv0 = bias[gq], bv1 = bias[gq + 8];
    __syncthreads();

    float* out0 = g_h1 + ((size_t)b * C1 + gq) * 1024 + cx * 256;
    float* out1 = g_h1 + ((size_t)b * C1 + gq + 8) * 1024 + cx * 256;

#pragma unroll
    for (int j = 0; j < 8; j += 2) {
        const int ntA = warp * 8 + j;
        float accA[4] = {0.f, 0.f, 0.f, 0.f}, accB[4] = {0.f, 0.f, 0.f, 0.f};
#pragma unroll
        for (int ks = 0; ks < 6; ks++) {
            int pA = ntA * 8 + gq;
            unsigned bA0 = __float_as_uint(xs[boff0[ks] + pA]);
            unsigned bA1 = __float_as_uint(xs[boff1[ks] + pA]);
            unsigned bB0 = __float_as_uint(xs[boff0[ks] + pA + 8]);
            unsigned bB1 = __float_as_uint(xs[boff1[ks] + pA + 8]);
            mma_tf32(accA, aw[ks][0], aw[ks][1], aw[ks][2], aw[ks][3], bA0, bA1);
            mma_tf32(accB, aw[ks][0], aw[ks][1], aw[ks][2], aw[ks][3], bB0, bB1);
        }
        int ppA = ntA * 4 + tq, ppB = ppA + 4;
        out0[ppA] = __uint_as_float(f2tf32(fmaxf(fmaxf(accA[0], accA[1]) + bv0, 0.f)));
        out1[ppA] = __uint_as_float(f2tf32(fmaxf(fmaxf(accA[2], accA[3]) + bv1, 0.f)));
        out0[ppB] = __uint_as_float(f2tf32(fmaxf(fmaxf(accB[0], accB[1]) + bv0, 0.f)));
        out1[ppB] = __uint_as_float(f2tf32(fmaxf(fmaxf(accB[2], accB[3]) + bv1, 0.f)));
    }
}

// ================= conv2 (MMA): 16->32 k5 pad2 + relu + maxpool2 =================
// A = W[32 co][K=80] (smem), B = h1[K][8 pos], pool in-register, node-major store.
#define XS2_STRIDE 524
#define WS2_STRIDE 84
__global__ void __launch_bounds__(256) conv2_kernel(const float* __restrict__ w,
                                                    const float* __restrict__ bias) {
    const int b = blockIdx.y, cx = blockIdx.x;       // chunk of 512 conv positions (of 1024)
    __shared__ float xs[16 * XS2_STRIDE];
    __shared__ float Ws[32 * WS2_STRIDE];
    const int tid = threadIdx.x;

    const float* hb = g_h1 + (size_t)b * C1 * 1024;
    for (int i = tid; i < 16 * 516; i += 256) {
        int r = i / 516, j = i % 516;
        int tg = cx * 512 + j - 2;
        xs[r * XS2_STRIDE + j] = ((unsigned)tg < 1024) ? hb[r * 1024 + tg] : 0.f;
    }
    for (int i = tid; i < 32 * 80; i += 256) {
        int co = i / 80, k = i % 80;
        Ws[co * WS2_STRIDE + k] = __uint_as_float(f2tf32(w[i]));
    }

    const int lane = tid & 31, warp = tid >> 5;
    const int gq = lane >> 2, tq = lane & 3;

    int boff0[10], boff1[10];
#pragma unroll
    for (int ks = 0; ks < 10; ks++) {
        int k0 = ks * 8 + tq, k1 = k0 + 4;
        boff0[ks] = (k0 / 5) * XS2_STRIDE + (k0 % 5);
        boff1[ks] = (k1 / 5) * XS2_STRIDE + (k1 % 5);
    }
    const float bvA0 = bias[gq],      bvA1 = bias[gq + 8];
    const float bvB0 = bias[16 + gq], bvB1 = bias[24 + gq];
    __syncthreads();

#pragma unroll
    for (int j = 0; j < 8; j += 2) {
        const int ntA = warp * 8 + j;
        float acc[2][2][4];
#pragma unroll
        for (int m = 0; m < 2; m++)
#pragma unroll
            for (int n = 0; n < 2; n++)
#pragma unroll
                for (int q = 0; q < 4; q++) acc[m][n][q] = 0.f;

#pragma unroll
        for (int ks = 0; ks < 10; ks++) {
            unsigned af[2][4];
#pragma unroll
            for (int m = 0; m < 2; m++) {
                int co0 = m * 16 + gq;
                af[m][0] = __float_as_uint(Ws[co0 * WS2_STRIDE + ks * 8 + tq]);
                af[m][1] = __float_as_uint(Ws[(co0 + 8) * WS2_STRIDE + ks * 8 + tq]);
                af[m][2] = __float_as_uint(Ws[co0 * WS2_STRIDE + ks * 8 + tq + 4]);
                af[m][3] = __float_as_uint(Ws[(co0 + 8) * WS2_STRIDE + ks * 8 + tq + 4]);
            }
            int pA = ntA * 8 + gq;
            unsigned bA0 = __float_as_uint(xs[boff0[ks] + pA]);
            unsigned bA1 = __float_as_uint(xs[boff1[ks] + pA]);
            unsigned bB0 = __float_as_uint(xs[boff0[ks] + pA + 8]);
            unsigned bB1 = __float_as_uint(xs[boff1[ks] + pA + 8]);
            mma_tf32(acc[0][0], af[0][0], af[0][1], af[0][2], af[0][3], bA0, bA1);
            mma_tf32(acc[1][0], af[1][0], af[1][1], af[1][2], af[1][3], bA0, bA1);
            mma_tf32(acc[0][1], af[0][0], af[0][1], af[0][2], af[0][3], bB0, bB1);
            mma_tf32(acc[1][1], af[1][0], af[1][1], af[1][2], af[1][3], bB0, bB1);
        }
        // epilogue: pool (adjacent n cols) + bias + relu, node-major store
        const size_t tb = (size_t)b * RT + cx * 256;
#pragma unroll
        for (int n = 0; n < 2; n++) {
            int t = (int)(ntA + n) * 4 + tq;
            float* g = g_h2 + (tb + t) * C2;
            g[gq]      = fmaxf(fmaxf(acc[0][n][0], acc[0][n][1]) + bvA0, 0.f);
            g[gq + 8]  = fmaxf(fmaxf(acc[0][n][2], acc[0][n][3]) + bvA1, 0.f);
            g[gq + 16] = fmaxf(fmaxf(acc[1][n][0], acc[1][n][1]) + bvB0, 0.f);
            g[gq + 24] = fmaxf(fmaxf(acc[1][n][2], acc[1][n][3]) + bvB1, 0.f);
        }
    }
}

// ---------------- fused GCN1 + GCN2 + time-mean partial ----------------
__device__ __forceinline__ void stencil_coeffs(int t, float& cL, float& cS, float& cR) {
    float dt = (t == 0 || t == RT - 1) ? DINV2 : DINV3;
    cS = dt * dt;
    cL = (t > 0)      ? dt * ((t - 1 == 0)      ? DINV2 : DINV3) : 0.f;
    cR = (t < RT - 1) ? dt * ((t + 1 == RT - 1) ? DINV2 : DINV3) : 0.f;
}

#define SW  136
#define SZ  132
#define SIN 36
#define GCN_SMEM_BYTES (56864 * 4)

__global__ void __launch_bounds__(256, 1) gcn_fused_kernel(
    const float* __restrict__ W1, const float* __restrict__ b1,
    const float* __restrict__ W2, const float* __restrict__ b2) {
    extern __shared__ float sm[];
    float* W2s = sm;
    float* W1s = sm + 17408;
    float* zs  = sm + 21760;
    float* g1s = sm + 39184;
    float* in_s = g1s;
    float* b1s = sm + 56608;
    float* b2s = sm + 56736;

    const int tid = threadIdx.x;
    const int b = blockIdx.y, chunk = blockIdx.x;
    const int t0 = chunk * 128;

    for (int i = tid; i < HID * HID; i += 256) {
        int r = i >> 7, c = i & 127;
        W2s[r * SW + c] = __uint_as_float(f2tf32(W2[i]));
    }
    for (int i = tid; i < 32 * HID; i += 256) {
        int r = i >> 7, c = i & 127;
        W1s[r * SW + c] = __uint_as_float(f2tf32(W1[i]));
    }
    if (tid < HID) { b1s[tid] = b1[tid]; b2s[tid] = b2[tid]; }
    for (int i = tid; i < 132 * 32; i += 256) {
        int r = i >> 5, c = i & 31;
        int t = t0 - 2 + r;
        float v = ((unsigned)t < RT) ? g_h2[((size_t)b * RT + t) * C2 + c] : 0.f;
        in_s[r * SIN + c] = __uint_as_float(f2tf32(v));
    }
    __syncthreads();

    const int w = tid >> 5, lane = tid & 31;
    const int gq = lane >> 2, tq = lane & 3;
    const int n0 = (w & 1) * 64, mg = w >> 1;

    // GEMM1
    {
        float acc[2][8][4];
#pragma unroll
        for (int mt = 0; mt < 2; mt++)
#pragma unroll
            for (int nt = 0; nt < 8; nt++)
#pragma unroll
                for (int q = 0; q < 4; q++) acc[mt][nt][q] = 0.f;

#pragma unroll
        for (int ks = 0; ks < 4; ks++) {
            unsigned bf[8][2];
#pragma unroll
            for (int nt = 0; nt < 8; nt++) {
                int nc = n0 + nt * 8 + gq;
                bf[nt][0] = __float_as_uint(W1s[(ks * 8 + tq) * SW + nc]);
                bf[nt][1] = __float_as_uint(W1s[(ks * 8 + tq + 4) * SW + nc]);
            }
#pragma unroll
            for (int mt = 0; mt < 2; mt++) {
                int r0 = (mg + mt * 4) * 16;
                unsigned a0 = __float_as_uint(in_s[(r0 + gq) * SIN + ks * 8 + tq]);
                unsigned a1 = __float_as_uint(in_s[(r0 + gq + 8) * SIN + ks * 8 + tq]);
                unsigned a2 = __float_as_uint(in_s[(r0 + gq) * SIN + ks * 8 + tq + 4]);
                unsigned a3 = __float_as_uint(in_s[(r0 + gq + 8) * SIN + ks * 8 + tq + 4]);
#pragma unroll
                for (int nt = 0; nt < 8; nt++)
                    mma_tf32(acc[mt][nt], a0, a1, a2, a3, bf[nt][0], bf[nt][1]);
            }
        }
#pragma unroll
        for (int mt = 0; mt < 2; mt++) {
            int r0 = (mg + mt * 4) * 16;
#pragma unroll
            for (int nt = 0; nt < 8; nt++) {
                int c0 = n0 + nt * 8 + tq * 2;
                zs[(r0 + gq) * SZ + c0]     = acc[mt][nt][0];
                zs[(r0 + gq) * SZ + c0 + 1] = acc[mt][nt][1];
                zs[(r0 + gq + 8) * SZ + c0]     = acc[mt][nt][2];
                zs[(r0 + gq + 8) * SZ + c0 + 1] = acc[mt][nt][3];
            }
        }
    }
    for (int e = tid; e < 4 * HID; e += 256) {
        int i = 128 + (e >> 7), c = e & 127;
        int t = t0 - 2 + i;
        float s = 0.f;
        if ((unsigned)t < RT) {
#pragma unroll 8
            for (int k = 0; k < 32; k++) s = fmaf(in_s[i * SIN + k], W1s[k * SW + c], s);
        }
        zs[i * SZ + c] = s;
    }
    __syncthreads();

    for (int e = tid; e < 130 * HID; e += 256) {
        int j = e >> 7, f = e & 127;
        int t = t0 - 1 + j;
        float g = 0.f;
        if ((unsigned)t < RT) {
            float cL, cS, cR; stencil_coeffs(t, cL, cS, cR);
            g = fmaf(cL, zs[j * SZ + f],
                fmaf(cS, zs[(j + 1) * SZ + f],
                fmaf(cR, zs[(j + 2) * SZ + f], b1s[f])));
            g = fmaxf(g, 0.f);
        }
        g1s[j * SZ + f] = __uint_as_float(f2tf32(g));
    }
    __syncthreads();

    // GEMM2
    {
        float acc[2][8][4];
#pragma unroll
        for (int mt = 0; mt < 2; mt++)
#pragma unroll
            for (int nt = 0; nt < 8; nt++)
#pragma unroll
                for (int q = 0; q < 4; q++) acc[mt][nt][q] = 0.f;

#pragma unroll
        for (int ks = 0; ks < 16; ks++) {
            unsigned bf[8][2];
#pragma unroll
            for (int nt = 0; nt < 8; nt++) {
                int nc = n0 + nt * 8 + gq;
                bf[nt][0] = __float_as_uint(W2s[(ks * 8 + tq) * SW + nc]);
                bf[nt][1] = __float_as_uint(W2s[(ks * 8 + tq + 4) * SW + nc]);
            }
#pragma unroll
            for (int mt = 0; mt < 2; mt++) {
                int r0 = (mg + mt * 4) * 16;
                unsigned a0 = __float_as_uint(g1s[(r0 + gq) * SZ + ks * 8 + tq]);
                unsigned a1 = __float_as_uint(g1s[(r0 + gq + 8) * SZ + ks * 8 + tq]);
                unsigned a2 = __float_as_uint(g1s[(r0 + gq) * SZ + ks * 8 + tq + 4]);
                unsigned a3 = __float_as_uint(g1s[(r0 + gq + 8) * SZ + ks * 8 + tq + 4]);
#pragma unroll
                for (int nt = 0; nt < 8; nt++)
                    mma_tf32(acc[mt][nt], a0, a1, a2, a3, bf[nt][0], bf[nt][1]);
            }
        }
#pragma unroll
        for (int mt = 0; mt < 2; mt++) {
            int r0 = (mg + mt * 4) * 16;
#pragma unroll
            for (int nt = 0; nt < 8; nt++) {
                int c0 = n0 + nt * 8 + tq * 2;
                zs[(r0 + gq) * SZ + c0]     = acc[mt][nt][0];
                zs[(r0 + gq) * SZ + c0 + 1] = acc[mt][nt][1];
                zs[(r0 + gq + 8) * SZ + c0]     = acc[mt][nt][2];
                zs[(r0 + gq + 8) * SZ + c0 + 1] = acc[mt][nt][3];
            }
        }
    }
    {
        int i2 = 128 + (tid >> 7), c = tid & 127;
        int t = t0 - 1 + i2;
        float s = 0.f;
        if ((unsigned)t < RT) {
#pragma unroll 8
            for (int k = 0; k < HID; k++) s = fmaf(g1s[i2 * SZ + k], W2s[k * SW + c], s);
        }
        zs[i2 * SZ + c] = s;
    }
    __syncthreads();

    {
        const int f = tid & 127, half = tid >> 7;
        const float bv = b2s[f];
        float s = 0.f;
#pragma unroll 4
        for (int r = 0; r < 64; r++) {
            int t = t0 + half * 64 + r;
            int i2 = half * 64 + r + 1;
            float cL, cS, cR; stencil_coeffs(t, cL, cS, cR);
            float g = fmaf(cL, zs[(i2 - 1) * SZ + f],
                      fmaf(cS, zs[i2 * SZ + f],
                      fmaf(cR, zs[(i2 + 1) * SZ + f], bv)));
            s += fmaxf(g, 0.f);
        }
        g_part[((size_t)(b * 8) + chunk * 2 + half) * HID + f] = s;
    }
}

// ---------------- mean + FC ----------------
__global__ void __launch_bounds__(128) fc_kernel(const float* __restrict__ fcw,
                                                 const float* __restrict__ fcb,
                                                 float* __restrict__ out) {
    const int b = blockIdx.x, tid = threadIdx.x;
    __shared__ float mean_s[HID];
    float s = 0.f;
#pragma unroll
    for (int i = 0; i < 8; i++) s += g_part[((size_t)b * 8 + i) * HID + tid];
    mean_s[tid] = s * (1.f / (float)RT);
    __syncthreads();
    if (tid < OUTF) {
        float acc = fcb[tid];
#pragma unroll 8
        for (int f = 0; f < HID; f++) acc = fmaf(mean_s[f], fcw[f * OUTF + tid], acc);
        out[(size_t)b * OUTF + tid] = acc;
    }
}

// ---------------- launch ----------------
extern "C" void kernel_launch(void* const* d_in, const int* in_sizes, int n_in,
                              void* d_out, int out_size) {
    const float* x       = (const float*)d_in[0];
    const float* conv1_w = (const float*)d_in[1];
    const float* conv1_b = (const float*)d_in[2];
    const float* conv2_w = (const float*)d_in[3];
    const float* conv2_b = (const float*)d_in[4];
    const float* gcn1_w  = (const float*)d_in[5];
    const float* gcn1_b  = (const float*)d_in[6];
    const float* gcn2_w  = (const float*)d_in[7];
    const float* gcn2_b  = (const float*)d_in[8];
    const float* fc_w    = (const float*)d_in[9];
    const float* fc_b    = (const float*)d_in[10];
    float* out = (float*)d_out;

    static bool attr_set = false;
    if (!attr_set) {
        cudaFuncSetAttribute(gcn_fused_kernel,
                             cudaFuncAttributeMaxDynamicSharedMemorySize, GCN_SMEM_BYTES);
        attr_set = true;
    }

    conv1_kernel<<<dim3(4, B_), 256>>>(x, conv1_w, conv1_b);
    conv2_kernel<<<dim3(2, B_), 256>>>(conv2_w, conv2_b);
    gcn_fused_kernel<<<dim3(4, B_), 256, GCN_SMEM_BYTES>>>(gcn1_w, gcn1_b, gcn2_w, gcn2_b);
    fc_kernel<<<B_, 128>>>(fc_w, fc_b, out);
}

// round 5
// speedup vs baseline: 4.8385x; 1.9812x over previous
#include <cuda_runtime.h>
#include <cstddef>

#define B_   1024
#define T_   2048
#define CIN  9
#define C1   16
#define C2   32
#define RT   512
#define HID  128
#define OUTF 64

#define DINV2 0.7071067811865475f
#define DINV3 0.5773502691896258f

// ---------------- scratch ----------------
__device__ float g_h1[(size_t)B_ * C1 * 1024];   // conv1 pooled out (tf32-rounded)
__device__ float g_h2[(size_t)B_ * RT * C2];     // conv2 pooled out, node-major
__device__ float g_mean[(size_t)B_ * HID];       // per-sample time-mean of g2

// ---------------- helpers ----------------
__device__ __forceinline__ unsigned f2tf32(float x) {
    unsigned u; asm("cvt.rna.tf32.f32 %0, %1;" : "=r"(u) : "f"(x)); return u;
}
__device__ __forceinline__ void mma_tf32(float c[4], unsigned a0, unsigned a1,
                                         unsigned a2, unsigned a3,
                                         unsigned b0, unsigned b1) {
    asm volatile("mma.sync.aligned.m16n8k8.row.col.f32.tf32.tf32.f32 "
                 "{%0,%1,%2,%3},{%4,%5,%6,%7},{%8,%9},{%0,%1,%2,%3};"
                 : "+f"(c[0]), "+f"(c[1]), "+f"(c[2]), "+f"(c[3])
                 : "r"(a0), "r"(a1), "r"(a2), "r"(a3), "r"(b0), "r"(b1));
}
// symmetric-normalized 3-pt stencil along t (chain graph + self loop)
__device__ __forceinline__ float stencil_apply(int t, float L, float S, float R) {
    float dt = (t == 0 || t == RT - 1) ? DINV2 : DINV3;
    float cL = (t > 0)      ? dt * ((t - 1 == 0)      ? DINV2 : DINV3) : 0.f;
    float cR = (t < RT - 1) ? dt * ((t + 1 == RT - 1) ? DINV2 : DINV3) : 0.f;
    return fmaf(cL, L, fmaf(dt * dt, S, cR * R));
}

// ================= conv1 (MMA): 9->16 k5 pad2 + relu + maxpool2 =================
#define XS1_STRIDE 524
__global__ void __launch_bounds__(256) conv1_kernel(const float* __restrict__ x,
                                                    const float* __restrict__ w,
                                                    const float* __restrict__ bias) {
    const int b = blockIdx.y, cx = blockIdx.x;
    __shared__ float xs[10 * XS1_STRIDE];
    const int tid = threadIdx.x;

    const float* xb = x + (size_t)b * CIN * T_;
    for (int i = tid; i < 10 * 516; i += 256) {
        int r = i / 516, j = i % 516;
        int tg = cx * 512 + j - 2;
        float v = (r < 9 && (unsigned)tg < T_) ? xb[r * T_ + tg] : 0.f;
        xs[r * XS1_STRIDE + j] = __uint_as_float(f2tf32(v));
    }

    const int lane = tid & 31, warp = tid >> 5;
    const int gq = lane >> 2, tq = lane & 3;

    unsigned aw[6][4];
    int boff0[6], boff1[6];
#pragma unroll
    for (int ks = 0; ks < 6; ks++) {
        int k0 = ks * 8 + tq, k1 = k0 + 4;
        aw[ks][0] = (k0 < 45) ? f2tf32(w[gq * 45 + k0])       : 0u;
        aw[ks][1] = (k0 < 45) ? f2tf32(w[(gq + 8) * 45 + k0]) : 0u;
        aw[ks][2] = (k1 < 45) ? f2tf32(w[gq * 45 + k1])       : 0u;
        aw[ks][3] = (k1 < 45) ? f2tf32(w[(gq + 8) * 45 + k1]) : 0u;
        boff0[ks] = (k0 / 5) * XS1_STRIDE + (k0 % 5);
        boff1[ks] = (k1 / 5) * XS1_STRIDE + (k1 % 5);
    }
    const float bv0 = bias[gq], bv1 = bias[gq + 8];
    __syncthreads();

    float* out0 = g_h1 + ((size_t)b * C1 + gq) * 1024 + cx * 256;
    float* out1 = g_h1 + ((size_t)b * C1 + gq + 8) * 1024 + cx * 256;

#pragma unroll
    for (int j = 0; j < 8; j += 2) {
        const int ntA = warp * 8 + j;
        float accA[4] = {0.f, 0.f, 0.f, 0.f}, accB[4] = {0.f, 0.f, 0.f, 0.f};
#pragma unroll
        for (int ks = 0; ks < 6; ks++) {
            int pA = ntA * 8 + gq;
            unsigned bA0 = __float_as_uint(xs[boff0[ks] + pA]);
            unsigned bA1 = __float_as_uint(xs[boff1[ks] + pA]);
            unsigned bB0 = __float_as_uint(xs[boff0[ks] + pA + 8]);
            unsigned bB1 = __float_as_uint(xs[boff1[ks] + pA + 8]);
            mma_tf32(accA, aw[ks][0], aw[ks][1], aw[ks][2], aw[ks][3], bA0, bA1);
            mma_tf32(accB, aw[ks][0], aw[ks][1], aw[ks][2], aw[ks][3], bB0, bB1);
        }
        int ppA = ntA * 4 + tq, ppB = ppA + 4;
        out0[ppA] = __uint_as_float(f2tf32(fmaxf(fmaxf(accA[0], accA[1]) + bv0, 0.f)));
        out1[ppA] = __uint_as_float(f2tf32(fmaxf(fmaxf(accA[2], accA[3]) + bv1, 0.f)));
        out0[ppB] = __uint_as_float(f2tf32(fmaxf(fmaxf(accB[0], accB[1]) + bv0, 0.f)));
        out1[ppB] = __uint_as_float(f2tf32(fmaxf(fmaxf(accB[2], accB[3]) + bv1, 0.f)));
    }
}

// ================= conv2 (MMA): 16->32 k5 pad2 + relu + maxpool2 =================
#define XS2_STRIDE 524
#define WS2_STRIDE 84
__global__ void __launch_bounds__(256) conv2_kernel(const float* __restrict__ w,
                                                    const float* __restrict__ bias) {
    const int b = blockIdx.y, cx = blockIdx.x;
    __shared__ float xs[16 * XS2_STRIDE];
    __shared__ float Ws[32 * WS2_STRIDE];
    const int tid = threadIdx.x;

    const float* hb = g_h1 + (size_t)b * C1 * 1024;
    for (int i = tid; i < 16 * 516; i += 256) {
        int r = i / 516, j = i % 516;
        int tg = cx * 512 + j - 2;
        xs[r * XS2_STRIDE + j] = ((unsigned)tg < 1024) ? hb[r * 1024 + tg] : 0.f;
    }
    for (int i = tid; i < 32 * 80; i += 256) {
        int co = i / 80, k = i % 80;
        Ws[co * WS2_STRIDE + k] = __uint_as_float(f2tf32(w[i]));
    }

    const int lane = tid & 31, warp = tid >> 5;
    const int gq = lane >> 2, tq = lane & 3;

    int boff0[10], boff1[10];
#pragma unroll
    for (int ks = 0; ks < 10; ks++) {
        int k0 = ks * 8 + tq, k1 = k0 + 4;
        boff0[ks] = (k0 / 5) * XS2_STRIDE + (k0 % 5);
        boff1[ks] = (k1 / 5) * XS2_STRIDE + (k1 % 5);
    }
    const float bvA0 = bias[gq],      bvA1 = bias[gq + 8];
    const float bvB0 = bias[16 + gq], bvB1 = bias[24 + gq];
    __syncthreads();

#pragma unroll
    for (int j = 0; j < 8; j += 2) {
        const int ntA = warp * 8 + j;
        float acc[2][2][4];
#pragma unroll
        for (int m = 0; m < 2; m++)
#pragma unroll
            for (int n = 0; n < 2; n++)
#pragma unroll
                for (int q = 0; q < 4; q++) acc[m][n][q] = 0.f;

#pragma unroll
        for (int ks = 0; ks < 10; ks++) {
            unsigned af[2][4];
#pragma unroll
            for (int m = 0; m < 2; m++) {
                int co0 = m * 16 + gq;
                af[m][0] = __float_as_uint(Ws[co0 * WS2_STRIDE + ks * 8 + tq]);
                af[m][1] = __float_as_uint(Ws[(co0 + 8) * WS2_STRIDE + ks * 8 + tq]);
                af[m][2] = __float_as_uint(Ws[co0 * WS2_STRIDE + ks * 8 + tq + 4]);
                af[m][3] = __float_as_uint(Ws[(co0 + 8) * WS2_STRIDE + ks * 8 + tq + 4]);
            }
            int pA = ntA * 8 + gq;
            unsigned bA0 = __float_as_uint(xs[boff0[ks] + pA]);
            unsigned bA1 = __float_as_uint(xs[boff1[ks] + pA]);
            unsigned bB0 = __float_as_uint(xs[boff0[ks] + pA + 8]);
            unsigned bB1 = __float_as_uint(xs[boff1[ks] + pA + 8]);
            mma_tf32(acc[0][0], af[0][0], af[0][1], af[0][2], af[0][3], bA0, bA1);
            mma_tf32(acc[1][0], af[1][0], af[1][1], af[1][2], af[1][3], bA0, bA1);
            mma_tf32(acc[0][1], af[0][0], af[0][1], af[0][2], af[0][3], bB0, bB1);
            mma_tf32(acc[1][1], af[1][0], af[1][1], af[1][2], af[1][3], bB0, bB1);
        }
        const size_t tb = (size_t)b * RT + cx * 256;
#pragma unroll
        for (int n = 0; n < 2; n++) {
            int t = (int)(ntA + n) * 4 + tq;
            float* g = g_h2 + (tb + t) * C2;
            g[gq]      = fmaxf(fmaxf(acc[0][n][0], acc[0][n][1]) + bvA0, 0.f);
            g[gq + 8]  = fmaxf(fmaxf(acc[0][n][2], acc[0][n][3]) + bvA1, 0.f);
            g[gq + 16] = fmaxf(fmaxf(acc[1][n][0], acc[1][n][1]) + bvB0, 0.f);
            g[gq + 24] = fmaxf(fmaxf(acc[1][n][2], acc[1][n][3]) + bvB1, 0.f);
        }
    }
}

// ======== fused GCN1 + GCN2 + mean: feature-major MMA, stencils via shuffles ========
// Per CTA: one sample, 8 chunks of 64 t. Output fragments are [feature][t];
// t-stencil = column stencil = shfl within tq groups. W1 frags in regs, W2^T in smem.
#define SW2   132   // W2s stride (k dim), 132 % 32 == 4
#define SG1   72    // g1s stride (t dim),  72 % 32 == 8
#define SIN2  36    // in_s stride (c dim), 36 % 32 == 4
#define GCN_SMEM_BYTES ((128 * SW2 + 128 * SG1 + 72 * SIN2) * 4)   // 114816

__global__ void __launch_bounds__(256, 2) gcn_fused_kernel(
    const float* __restrict__ W1, const float* __restrict__ b1,
    const float* __restrict__ W2, const float* __restrict__ b2) {
    extern __shared__ float sm[];
    float* W2s  = sm;                        // [128][SW2]  W2^T: W2s[m][k] = W2[k][m]
    float* g1s  = sm + 128 * SW2;            // [128 feats][SG1 t-cols]
    float* in_s = g1s + 128 * SG1;           // [72 t-rows][SIN2]

    const int tid = threadIdx.x;
    const int b = blockIdx.x;
    const int warp = tid >> 5, lane = tid & 31;
    const int gq = lane >> 2, tq = lane & 3;
    const int fbase = warp * 16;
    const unsigned FULL = 0xffffffffu;

    // W2^T into smem (tf32), once per CTA
    for (int i = tid; i < HID * HID; i += 256) {
        int k = i >> 7, m = i & 127;
        W2s[m * SW2 + k] = __uint_as_float(f2tf32(W2[i]));
    }
    // W1^T fragments in registers: A(m=feat, k=ci)
    unsigned aw1[4][4];
#pragma unroll
    for (int ks = 0; ks < 4; ks++) {
        int k0 = ks * 8 + tq;
        aw1[ks][0] = f2tf32(W1[k0 * HID + fbase + gq]);
        aw1[ks][1] = f2tf32(W1[k0 * HID + fbase + 8 + gq]);
        aw1[ks][2] = f2tf32(W1[(k0 + 4) * HID + fbase + gq]);
        aw1[ks][3] = f2tf32(W1[(k0 + 4) * HID + fbase + 8 + gq]);
    }
    const float b1v0 = b1[fbase + gq], b1v1 = b1[fbase + 8 + gq];
    const float b2v0 = b2[fbase + gq], b2v1 = b2[fbase + 8 + gq];
    float sum0 = 0.f, sum1 = 0.f;
    __syncthreads();

    for (int chunk = 0; chunk < 8; chunk++) {
        const int t0 = chunk * 64;
        // load in: row r <-> t = t0-2+r, 72 rows x 32 feats
        for (int i = tid; i < 72 * 32; i += 256) {
            int r = i >> 5, c = i & 31;
            int t = t0 - 2 + r;
            float v = ((unsigned)t < RT) ? g_h2[((size_t)b * RT + t) * C2 + c] : 0.f;
            in_s[r * SIN2 + c] = __uint_as_float(f2tf32(v));
        }
        __syncthreads();

        // ---- GEMM1: z1[m=16 feats/warp][n=72 t-cols], col n <-> t = t0-2+n ----
        float acc[9][4];
#pragma unroll
        for (int nt = 0; nt < 9; nt++)
#pragma unroll
            for (int q = 0; q < 4; q++) acc[nt][q] = 0.f;
#pragma unroll
        for (int ks = 0; ks < 4; ks++)
#pragma unroll
            for (int nt = 0; nt < 9; nt++) {
                unsigned bb0 = __float_as_uint(in_s[(nt * 8 + gq) * SIN2 + ks * 8 + tq]);
                unsigned bb1 = __float_as_uint(in_s[(nt * 8 + gq) * SIN2 + ks * 8 + tq + 4]);
                mma_tf32(acc[nt], aw1[ks][0], aw1[ks][1], aw1[ks][2], aw1[ks][3], bb0, bb1);
            }

        // ---- stencil1 (cols) + bias + relu + tf32 -> g1s[feat][idx], idx = n-1 (n in 1..66) ----
#pragma unroll
        for (int h = 0; h < 2; h++) {
            const int rowf = fbase + 8 * h + gq;
            const float bv = h ? b1v1 : b1v0;
#pragma unroll
            for (int nt = 0; nt < 9; nt++) {
                float zE = acc[nt][2 * h], zO = acc[nt][2 * h + 1];
                float pO = __shfl_up_sync(FULL, zO, 1, 4);
                float nEv = __shfl_down_sync(FULL, zE, 1, 4);
                float pT = (nt > 0) ? __shfl_sync(FULL, acc[nt - 1][2 * h + 1], 3, 4) : 0.f;
                float nT = (nt < 8) ? __shfl_sync(FULL, acc[nt + 1][2 * h], 0, 4) : 0.f;
                float Le = (tq == 0) ? pT : pO;
                float Ro = (tq == 3) ? nT : nEv;
                int ne = nt * 8 + 2 * tq;            // even col
                int te = t0 - 2 + ne, to = te + 1;
                if (ne >= 2 && ne <= 66) {
                    float y = ((unsigned)te < RT)
                        ? fmaxf(stencil_apply(te, Le, zE, zO) + bv, 0.f) : 0.f;
                    g1s[rowf * SG1 + ne - 1] = __uint_as_float(f2tf32(y));
                }
                int no = ne + 1;                     // odd col
                if (no <= 66) {
                    float y = ((unsigned)to < RT)
                        ? fmaxf(stencil_apply(to, zE, zO, Ro) + bv, 0.f) : 0.f;
                    g1s[rowf * SG1 + no - 1] = __uint_as_float(f2tf32(y));
                }
            }
        }
        __syncthreads();

        // ---- GEMM2: z2[m][n=72 t-cols], col n <-> t = t0-1+n; B = g1s, A = W2s ----
        float acc2[9][4];
#pragma unroll
        for (int nt = 0; nt < 9; nt++)
#pragma unroll
            for (int q = 0; q < 4; q++) acc2[nt][q] = 0.f;
#pragma unroll 4
        for (int ks = 0; ks < 16; ks++) {
            int k0 = ks * 8 + tq;
            unsigned a0 = __float_as_uint(W2s[(fbase + gq) * SW2 + k0]);
            unsigned a1 = __float_as_uint(W2s[(fbase + 8 + gq) * SW2 + k0]);
            unsigned a2 = __float_as_uint(W2s[(fbase + gq) * SW2 + k0 + 4]);
            unsigned a3 = __float_as_uint(W2s[(fbase + 8 + gq) * SW2 + k0 + 4]);
#pragma unroll
            for (int nt = 0; nt < 9; nt++) {
                unsigned bb0 = __float_as_uint(g1s[k0 * SG1 + nt * 8 + gq]);
                unsigned bb1 = __float_as_uint(g1s[(k0 + 4) * SG1 + nt * 8 + gq]);
                mma_tf32(acc2[nt], a0, a1, a2, a3, bb0, bb1);
            }
        }

        // ---- stencil2 + bias + relu + accumulate mean (valid n in 1..64, t = t0-1+n) ----
#pragma unroll
        for (int h = 0; h < 2; h++) {
            const float bv = h ? b2v1 : b2v0;
            float lsum = 0.f;
#pragma unroll
            for (int nt = 0; nt < 9; nt++) {
                float zE = acc2[nt][2 * h], zO = acc2[nt][2 * h + 1];
                float pO = __shfl_up_sync(FULL, zO, 1, 4);
                float nEv = __shfl_down_sync(FULL, zE, 1, 4);
                float pT = (nt > 0) ? __shfl_sync(FULL, acc2[nt - 1][2 * h + 1], 3, 4) : 0.f;
                float nT = (nt < 8) ? __shfl_sync(FULL, acc2[nt + 1][2 * h], 0, 4) : 0.f;
                float Le = (tq == 0) ? pT : pO;
                float Ro = (tq == 3) ? nT : nEv;
                int ne = nt * 8 + 2 * tq;
                int te = t0 - 1 + ne, to = te + 1;
                if (ne >= 2 && ne <= 64)
                    lsum += fmaxf(stencil_apply(te, Le, zE, zO) + bv, 0.f);
                int no = ne + 1;
                if (no <= 64)
                    lsum += fmaxf(stencil_apply(to, zE, zO, Ro) + bv, 0.f);
            }
            if (h) sum1 += lsum; else sum0 += lsum;
        }
    }

    // reduce over tq lanes (each col handled by one tq) and write mean
    sum0 += __shfl_xor_sync(FULL, sum0, 1);
    sum0 += __shfl_xor_sync(FULL, sum0, 2);
    sum1 += __shfl_xor_sync(FULL, sum1, 1);
    sum1 += __shfl_xor_sync(FULL, sum1, 2);
    if (tq == 0) {
        g_mean[(size_t)b * HID + fbase + gq]     = sum0 * (1.f / (float)RT);
        g_mean[(size_t)b * HID + fbase + 8 + gq] = sum1 * (1.f / (float)RT);
    }
}

// ---------------- FC ----------------
__global__ void __launch_bounds__(128) fc_kernel(const float* __restrict__ fcw,
                                                 const float* __restrict__ fcb,
                                                 float* __restrict__ out) {
    const int b = blockIdx.x, tid = threadIdx.x;
    __shared__ float mean_s[HID];
    mean_s[tid] = g_mean[(size_t)b * HID + tid];
    __syncthreads();
    if (tid < OUTF) {
        float acc = fcb[tid];
#pragma unroll 8
        for (int f = 0; f < HID; f++) acc = fmaf(mean_s[f], fcw[f * OUTF + tid], acc);
        out[(size_t)b * OUTF + tid] = acc;
    }
}

// ---------------- launch ----------------
extern "C" void kernel_launch(void* const* d_in, const int* in_sizes, int n_in,
                              void* d_out, int out_size) {
    const float* x       = (const float*)d_in[0];
    const float* conv1_w = (const float*)d_in[1];
    const float* conv1_b = (const float*)d_in[2];
    const float* conv2_w = (const float*)d_in[3];
    const float* conv2_b = (const float*)d_in[4];
    const float* gcn1_w  = (const float*)d_in[5];
    const float* gcn1_b  = (const float*)d_in[6];
    const float* gcn2_w  = (const float*)d_in[7];
    const float* gcn2_b  = (const float*)d_in[8];
    const float* fc_w    = (const float*)d_in[9];
    const float* fc_b    = (const float*)d_in[10];
    float* out = (float*)d_out;

    static bool attr_set = false;
    if (!attr_set) {
        cudaFuncSetAttribute(gcn_fused_kernel,
                             cudaFuncAttributeMaxDynamicSharedMemorySize, GCN_SMEM_BYTES);
        attr_set = true;
    }

    conv1_kernel<<<dim3(4, B_), 256>>>(x, conv1_w, conv1_b);
    conv2_kernel<<<dim3(2, B_), 256>>>(conv2_w, conv2_b);
    gcn_fused_kernel<<<B_, 256, GCN_SMEM_BYTES>>>(gcn1_w, gcn1_b, gcn2_w, gcn2_b);
    fc_kernel<<<B_, 128>>>(fc_w, fc_b, out);
}